// round 9
// baseline (speedup 1.0000x reference)
#include <cuda_runtime.h>
#include <cuda_fp16.h>
#include <cstdint>
#include <math.h>

// Problem constants
#define BB 4
#define NN 2048
#define DD 512
#define HH 8
#define HD 64
#define NC 2048
#define RR (BB*NN)

// Scratch (device globals; no allocation allowed)
__device__ __half g_xnh[(size_t)RR * DD];   // half: layernorm(x); later o_input
__device__ __half g_mmh[(size_t)RR * NC];   // half: silu(xn @ uvqk) [u|v|q|k]
__device__ __half g_wh [(size_t)NC * DD];   // half: uvqk transposed [n][k]
__device__ __half g_owh[(size_t)DD * DD];   // half: o_weight [n][k]
__device__ float  g_at [(size_t)RR * DD];   // fp32 attention output

__device__ __forceinline__ float silu_f(float v) {
    return v / (1.0f + __expf(-v));
}

__device__ __forceinline__ uint32_t smem_u32(const void* p) {
    uint32_t a;
    asm("{ .reg .u64 t; cvta.to.shared.u64 t, %1; cvt.u32.u64 %0, t; }"
        : "=r"(a) : "l"(p));
    return a;
}

__device__ __forceinline__ void ldmA(uint32_t* a, uint32_t addr) {
    asm volatile("ldmatrix.sync.aligned.m8n8.x4.shared.b16 {%0,%1,%2,%3}, [%4];"
                 : "=r"(a[0]), "=r"(a[1]), "=r"(a[2]), "=r"(a[3]) : "r"(addr));
}

__device__ __forceinline__ void ldmT(uint32_t* a, uint32_t addr) {
    asm volatile("ldmatrix.sync.aligned.m8n8.x4.trans.shared.b16 {%0,%1,%2,%3}, [%4];"
                 : "=r"(a[0]), "=r"(a[1]), "=r"(a[2]), "=r"(a[3]) : "r"(addr));
}

// fp16 mma, fp32 accumulate: D += A(16x16) * B(16x8)
__device__ __forceinline__ void mma_f16(float* d, const uint32_t* a,
                                        uint32_t b0, uint32_t b1) {
    asm volatile(
        "mma.sync.aligned.m16n8k16.row.col.f32.f16.f16.f32 "
        "{%0,%1,%2,%3},{%4,%5,%6,%7},{%8,%9},{%0,%1,%2,%3};"
        : "+f"(d[0]), "+f"(d[1]), "+f"(d[2]), "+f"(d[3])
        : "r"(a[0]), "r"(a[1]), "r"(a[2]), "r"(a[3]), "r"(b0), "r"(b1));
}

__device__ __forceinline__ void cp16(uint32_t dst, const void* src) {
    asm volatile("cp.async.cg.shared.global [%0], [%1], 16;" :: "r"(dst), "l"(src));
}
#define CP_COMMIT() asm volatile("cp.async.commit_group;" ::: "memory")
#define CP_WAIT(n)  asm volatile("cp.async.wait_group %0;" :: "n"(n) : "memory")

// ldmatrix-x4 per-lane byte offset for a 16x16-half A block, stride in halfs
__device__ __forceinline__ uint32_t ldm_off_h(int lane, int stride_halfs) {
    int r = (lane & 7) + ((lane >> 3) & 1) * 8;
    int c16 = (lane >> 4);
    return (uint32_t)(r * stride_halfs * 2 + c16 * 16);
}

// ldmatrix-x4 per-lane byte offset for B (K-major [n][k]): 2 n-frags x k16.
__device__ __forceinline__ uint32_t ldm_off_b(int lane, int stride_halfs) {
    int r = lane & 7;
    int m = lane >> 3;
    return (uint32_t)(((m >> 1) * 8 + r) * stride_halfs * 2 + (m & 1) * 16);
}

// ---------------------------------------------------------------------------
// LayerNorm: fp32 math, half output
// ---------------------------------------------------------------------------
__global__ void ln_kernel(const float* __restrict__ x) {
    int row = blockIdx.x;
    int t = threadIdx.x;
    float4 v = ((const float4*)(x + (size_t)row * DD))[t];
    float s  = v.x + v.y + v.z + v.w;
    float s2 = v.x*v.x + v.y*v.y + v.z*v.z + v.w*v.w;
#pragma unroll
    for (int o = 16; o > 0; o >>= 1) {
        s  += __shfl_xor_sync(0xffffffffu, s,  o);
        s2 += __shfl_xor_sync(0xffffffffu, s2, o);
    }
    __shared__ float sh[8];
    if ((t & 31) == 0) { sh[t >> 5] = s; sh[4 + (t >> 5)] = s2; }
    __syncthreads();
    s  = sh[0] + sh[1] + sh[2] + sh[3];
    s2 = sh[4] + sh[5] + sh[6] + sh[7];
    float mu  = s * (1.0f / DD);
    float var = fmaxf(s2 * (1.0f / DD) - mu * mu, 0.0f);
    float r   = rsqrtf(var + 1e-6f);
    __half2 h0 = __floats2half2_rn((v.x - mu) * r, (v.y - mu) * r);
    __half2 h1 = __floats2half2_rn((v.z - mu) * r, (v.w - mu) * r);
    ((__half2*)(g_xnh + (size_t)row * DD))[2 * t]     = h0;
    ((__half2*)(g_xnh + (size_t)row * DD))[2 * t + 1] = h1;
}

__global__ void gated_ln_kernel() {
    int row = blockIdx.x;
    int t = threadIdx.x;
    float4 v = ((const float4*)(g_at + (size_t)row * DD))[t];
    float s  = v.x + v.y + v.z + v.w;
    float s2 = v.x*v.x + v.y*v.y + v.z*v.z + v.w*v.w;
#pragma unroll
    for (int o = 16; o > 0; o >>= 1) {
        s  += __shfl_xor_sync(0xffffffffu, s,  o);
        s2 += __shfl_xor_sync(0xffffffffu, s2, o);
    }
    __shared__ float sh[8];
    if ((t & 31) == 0) { sh[t >> 5] = s; sh[4 + (t >> 5)] = s2; }
    __syncthreads();
    s  = sh[0] + sh[1] + sh[2] + sh[3];
    s2 = sh[4] + sh[5] + sh[6] + sh[7];
    float mu  = s * (1.0f / DD);
    float var = fmaxf(s2 * (1.0f / DD) - mu * mu, 0.0f);
    float r   = rsqrtf(var + 1e-6f);
    __half2 u01 = ((const __half2*)(g_mmh + (size_t)row * NC))[2 * t];
    __half2 u23 = ((const __half2*)(g_mmh + (size_t)row * NC))[2 * t + 1];
    float2 u0 = __half22float2(u01), u1 = __half22float2(u23);
    __half2 h0 = __floats2half2_rn(u0.x * (v.x - mu) * r, u0.y * (v.y - mu) * r);
    __half2 h1 = __floats2half2_rn(u1.x * (v.z - mu) * r, u1.y * (v.w - mu) * r);
    ((__half2*)(g_xnh + (size_t)row * DD))[2 * t]     = h0;
    ((__half2*)(g_xnh + (size_t)row * DD))[2 * t + 1] = h1;
}

// ---------------------------------------------------------------------------
// Weight converts
// ---------------------------------------------------------------------------
__global__ void cvt_w_t(const float* __restrict__ W) {
    __shared__ float tbuf[32][33];
    int lx = threadIdx.x & 31, ly = threadIdx.x >> 5;
    int bx = blockIdx.x, by = blockIdx.y;
    int col = bx * 32 + lx;
#pragma unroll
    for (int i = 0; i < 32; i += 8)
        tbuf[ly + i][lx] = W[(size_t)(by * 32 + ly + i) * NC + col];
    __syncthreads();
    int ok = by * 32 + lx;
#pragma unroll
    for (int i = 0; i < 32; i += 8)
        g_wh[(size_t)(bx * 32 + ly + i) * DD + ok] = __float2half_rn(tbuf[lx][ly + i]);
}

__global__ void cvt_ow(const float* __restrict__ W) {
    int i = blockIdx.x * 256 + threadIdx.x;
    float4 v = ((const float4*)W)[i];
    __half2 h0 = __floats2half2_rn(v.x, v.y);
    __half2 h1 = __floats2half2_rn(v.z, v.w);
    ((__half2*)g_owh)[2 * i]     = h0;
    ((__half2*)g_owh)[2 * i + 1] = h1;
}

// ---------------------------------------------------------------------------
// fp16 mma GEMM. Block tile 128x128, BK=64 halfs, 8 warps (2m x 4n),
// warp tile 64x32, cp.async double buffer, ONE sync per K-chunk.
// ---------------------------------------------------------------------------
#define SAH   72
#define ASBH  (128 * SAH * 2)
#define GSMEMH (4 * ASBH)

template <int MODE>
__global__ __launch_bounds__(256)
void gemm_h(const __half* __restrict__ A, const __half* __restrict__ Bm,
            __half* __restrict__ Ch, float* __restrict__ Cf,
            const float* __restrict__ bias, const float* __restrict__ xres,
            int Nn, int K) {
    extern __shared__ char smem[];
    uint32_t sAu = smem_u32(smem);
    uint32_t sBu = sAu + 2 * ASBH;

    int tid = threadIdx.x;
    int wid = tid >> 5, lane = tid & 31;
    int m0 = blockIdx.y * 128, n0 = blockIdx.x * 128;
    int wm = (wid & 1) * 64;
    int wn = (wid >> 1) * 32;

    float acc[4][4][4];
#pragma unroll
    for (int i = 0; i < 4; i++)
#pragma unroll
        for (int j = 0; j < 4; j++)
#pragma unroll
            for (int r = 0; r < 4; r++) acc[i][j][r] = 0.0f;

    const int NCH = K / 64;
    uint32_t aoff = ldm_off_h(lane, SAH);
    uint32_t boff = (uint32_t)(wn * SAH * 2) + ldm_off_b(lane, SAH);

    auto stageA = [&](int c, int s) {
#pragma unroll
        for (int i = 0; i < 4; i++) {
            int idx = tid + i * 256;
            int row = idx >> 3, seg = idx & 7;
            cp16(sAu + s * ASBH + (row * SAH + seg * 8) * 2,
                 A + (size_t)(m0 + row) * K + c * 64 + seg * 8);
        }
    };
    auto stageB = [&](int c, int s) {
#pragma unroll
        for (int i = 0; i < 4; i++) {
            int idx = tid + i * 256;
            int row = idx >> 3, seg = idx & 7;
            cp16(sBu + s * ASBH + (row * SAH + seg * 8) * 2,
                 Bm + (size_t)(n0 + row) * K + c * 64 + seg * 8);
        }
    };

    stageA(0, 0); stageB(0, 0); CP_COMMIT();

    for (int c = 0; c < NCH; c++) {
        int s = c & 1;
        CP_WAIT(0);
        __syncthreads();    // chunk c visible; all warps done computing s^1
        if (c + 1 < NCH) {
            stageA(c + 1, s ^ 1); stageB(c + 1, s ^ 1); CP_COMMIT();
        }

#pragma unroll
        for (int ks = 0; ks < 4; ks++) {
            uint32_t b01[4], b23[4];
            ldmA(b01, sBu + s * ASBH + boff + ks * 32);
            ldmA(b23, sBu + s * ASBH + boff + 16 * SAH * 2 + ks * 32);
#pragma unroll
            for (int im = 0; im < 4; im++) {
                uint32_t a[4];
                ldmA(a, sAu + s * ASBH + (uint32_t)((wm + im * 16) * SAH * 2 + ks * 32) + aoff);
                mma_f16(acc[im][0], a, b01[0], b01[1]);
                mma_f16(acc[im][1], a, b01[2], b01[3]);
                mma_f16(acc[im][2], a, b23[0], b23[1]);
                mma_f16(acc[im][3], a, b23[2], b23[3]);
            }
        }
    }

    int er = lane >> 2, ec = (lane & 3) * 2;
#pragma unroll
    for (int im = 0; im < 4; im++) {
#pragma unroll
        for (int in = 0; in < 4; in++) {
            int row = m0 + wm + im * 16 + er;
            int col = n0 + wn + in * 8 + ec;
#pragma unroll
            for (int h = 0; h < 2; h++) {
                float v0 = acc[im][in][2 * h + 0];
                float v1 = acc[im][in][2 * h + 1];
                int rr = row + 8 * h;
                if (MODE == 0) {
                    __half2 o = __floats2half2_rn(silu_f(v0), silu_f(v1));
                    *(__half2*)(Ch + (size_t)rr * Nn + col) = o;
                } else {
                    float2 bi = *(const float2*)(bias + col);
                    float2 xr = *(const float2*)(xres + (size_t)rr * Nn + col);
                    float2 o; o.x = v0 + bi.x + xr.x; o.y = v1 + bi.y + xr.y;
                    *(float2*)(Cf + (size_t)rr * Nn + col) = o;
                }
            }
        }
    }
}

// ---------------------------------------------------------------------------
// Fused causal silu-attention, fp16 mma, cross-iteration phase pipeline:
// iter kt: wait; sync; stage KV(kt+1); phase2(tile kt-1); phase1(tile kt).
// ONE sync per kv-tile. 3 KV buffers, 2 Ss buffers. Smem 81 KB -> 2 CTA/SM.
// ---------------------------------------------------------------------------
#define SATH  72
#define ATILEH (64 * SATH * 2)            // 9216
#define HOFF_K (1 * ATILEH)               // K[3]
#define HOFF_V (4 * ATILEH)               // V[3]
#define HOFF_S (7 * ATILEH)               // Ss[2]
#define ASMEMH (9 * ATILEH)               // 82944

__global__ __launch_bounds__(256)
void attn_mma() {
    extern __shared__ char smem[];
    uint32_t sbase = smem_u32(smem);
    uint32_t Qsu = sbase;

    int qt = blockIdx.x, h = blockIdx.y, b = blockIdx.z;
    int tid = threadIdx.x;
    int wid = tid >> 5, lane = tid & 31;
    int wm = (wid & 1) * 32;
    int wn = (wid >> 1) * 16;
    const int qcol = 1024 + h * HD;
    const int kcol = 1536 + h * HD;
    const int vcol = 512 + h * HD;
    uint32_t aoff = ldm_off_h(lane, SATH);
    uint32_t koff = (uint32_t)(wn * SATH * 2) + ldm_off_b(lane, SATH);

    // V ldmatrix.x4.trans per-lane address pieces
    int tl = lane & 7;
    int tmi = lane >> 3;
    int tkr = (tmi & 1) * 8 + tl;
    int tnc = (tmi >> 1) * 8;

    auto stageQ = [&]() {
#pragma unroll
        for (int i = 0; i < 2; i++) {
            int idx = tid + i * 256;
            int row = idx >> 3, seg = idx & 7;
            cp16(Qsu + (row * SATH + seg * 8) * 2,
                 g_mmh + (size_t)(b * NN + qt * 64 + row) * NC + qcol + seg * 8);
        }
    };
    auto stageKV = [&](int kt, int s3) {
        uint32_t kd = sbase + HOFF_K + s3 * ATILEH;
        uint32_t vd = sbase + HOFF_V + s3 * ATILEH;
#pragma unroll
        for (int i = 0; i < 2; i++) {
            int idx = tid + i * 256;
            int row = idx >> 3, seg = idx & 7;
            size_t gb = (size_t)(b * NN + kt * 64 + row) * NC;
            uint32_t so = (uint32_t)((row * SATH + seg * 8) * 2);
            cp16(kd + so, g_mmh + gb + kcol + seg * 8);
            cp16(vd + so, g_mmh + gb + vcol + seg * 8);
        }
    };

    // phase2: O += Ss[sb2] @ V[v3]
    auto phase2 = [&](int v3, int sb2, float oacc[2][2][4]) {
        uint32_t Vsu = sbase + HOFF_V + v3 * ATILEH;
        uint32_t Ssu = sbase + HOFF_S + sb2 * ATILEH;
#pragma unroll
        for (int ks = 0; ks < 4; ks++) {
            uint32_t bv[4];
            ldmT(bv, Vsu + (uint32_t)(((ks * 16 + tkr) * SATH + wn + tnc) * 2));
#pragma unroll
            for (int im = 0; im < 2; im++) {
                uint32_t a[4];
                ldmA(a, Ssu + (uint32_t)((wm + im * 16) * SATH * 2 + ks * 32) + aoff);
                mma_f16(oacc[im][0], a, bv[0], bv[1]);
                mma_f16(oacc[im][1], a, bv[2], bv[3]);
            }
        }
    };

    float oacc[2][2][4];
#pragma unroll
    for (int i = 0; i < 2; i++)
#pragma unroll
        for (int j = 0; j < 2; j++)
#pragma unroll
            for (int r = 0; r < 4; r++) oacc[i][j][r] = 0.0f;

    const float inv_n = 1.0f / (float)NN;
    int er = lane >> 2, ec = (lane & 3) * 2;
    const int nkt = qt + 1;

    stageQ(); stageKV(0, 0); CP_COMMIT();

    int s3 = 0;                       // kt % 3
    for (int kt = 0; kt < nkt; kt++) {
        CP_WAIT(0);
        __syncthreads();   // KV tile kt + Ss[kt-1] visible; buffers reusable

        int n3 = (s3 == 2) ? 0 : s3 + 1;
        if (kt + 1 < nkt) { stageKV(kt + 1, n3); CP_COMMIT(); }

        // Phase 2 for tile kt-1 (overlaps with in-flight stage of kt+1)
        if (kt > 0) {
            int p3 = (s3 == 0) ? 2 : s3 - 1;     // (kt-1) % 3
            phase2(p3, (kt - 1) & 1, oacc);
        }

        // Phase 1: S = Q @ K[kt]^T
        uint32_t Ksu = sbase + HOFF_K + s3 * ATILEH;
        float sacc[2][2][4];
#pragma unroll
        for (int i = 0; i < 2; i++)
#pragma unroll
            for (int j = 0; j < 2; j++)
#pragma unroll
                for (int r = 0; r < 4; r++) sacc[i][j][r] = 0.0f;
#pragma unroll
        for (int ks = 0; ks < 4; ks++) {
            uint32_t bk[4];
            ldmA(bk, Ksu + koff + ks * 32);
#pragma unroll
            for (int im = 0; im < 2; im++) {
                uint32_t a[4];
                ldmA(a, Qsu + (uint32_t)((wm + im * 16) * SATH * 2 + ks * 32) + aoff);
                mma_f16(sacc[im][0], a, bk[0], bk[1]);
                mma_f16(sacc[im][1], a, bk[2], bk[3]);
            }
        }

        // silu + causal mask -> Ss[kt & 1]
        __half* Ssw = (__half*)(smem + HOFF_S + (kt & 1) * ATILEH);
        bool diag = (kt == qt);
#pragma unroll
        for (int im = 0; im < 2; im++) {
#pragma unroll
            for (int in = 0; in < 2; in++) {
#pragma unroll
                for (int hh = 0; hh < 2; hh++) {
                    int i = wm + im * 16 + er + 8 * hh;
                    int j = wn + in * 8 + ec;
                    float v0 = silu_f(sacc[im][in][2 * hh + 0]);
                    float v1 = silu_f(sacc[im][in][2 * hh + 1]);
                    if (diag) {
                        if (j > i) v0 = 0.0f;
                        if (j + 1 > i) v1 = 0.0f;
                    }
                    *(__half2*)(Ssw + i * SATH + j) = __floats2half2_rn(v0, v1);
                }
            }
        }

        s3 = n3;
    }

    // Final phase2 for tile nkt-1
    __syncthreads();
    {
        int p3 = (nkt - 1) % 3;
        phase2(p3, (nkt - 1) & 1, oacc);
    }

    // Write O tile (scaled by 1/N)
#pragma unroll
    for (int im = 0; im < 2; im++) {
#pragma unroll
        for (int in = 0; in < 2; in++) {
#pragma unroll
            for (int hh = 0; hh < 2; hh++) {
                int n = qt * 64 + wm + im * 16 + er + 8 * hh;
                int j = h * HD + wn + in * 8 + ec;
                float2 o;
                o.x = oacc[im][in][2 * hh + 0] * inv_n;
                o.y = oacc[im][in][2 * hh + 1] * inv_n;
                *(float2*)(g_at + (size_t)(b * NN + n) * DD + j) = o;
            }
        }
    }
}

// ---------------------------------------------------------------------------
extern "C" void kernel_launch(void* const* d_in, const int* in_sizes, int n_in,
                              void* d_out, int out_size) {
    const float* x    = (const float*)d_in[0];
    const float* uvqk = (const float*)d_in[2];
    const float* ow   = (const float*)d_in[3];
    const float* ob   = (const float*)d_in[4];
    float* out = (float*)d_out;

    void *pxnh, *pmmh, *pwh, *powh;
    cudaGetSymbolAddress(&pxnh, g_xnh);
    cudaGetSymbolAddress(&pmmh, g_mmh);
    cudaGetSymbolAddress(&pwh,  g_wh);
    cudaGetSymbolAddress(&powh, g_owh);

    cudaFuncSetAttribute(gemm_h<0>, cudaFuncAttributeMaxDynamicSharedMemorySize, GSMEMH);
    cudaFuncSetAttribute(gemm_h<1>, cudaFuncAttributeMaxDynamicSharedMemorySize, GSMEMH);
    cudaFuncSetAttribute(attn_mma, cudaFuncAttributeMaxDynamicSharedMemorySize, ASMEMH);

    // 0. weight converts
    cvt_w_t<<<dim3(NC / 32, DD / 32), 256>>>(uvqk);
    cvt_ow<<<DD * DD / 1024, 256>>>(ow);
    // 1. xn = layernorm(x) -> half
    ln_kernel<<<RR, 128>>>(x);
    // 2. mm = silu(xn @ uvqk) -> half
    gemm_h<0><<<dim3(NC / 128, RR / 128), 256, GSMEMH>>>(
        (const __half*)pxnh, (const __half*)pwh, (__half*)pmmh, nullptr,
        nullptr, nullptr, NC, DD);
    // 3. attention
    attn_mma<<<dim3(NN / 64, HH, BB), 256, ASMEMH>>>();
    // 4. o_input = u * layernorm(attn) -> half
    gated_ln_kernel<<<RR, 128>>>();
    // 5. out = o_input @ o_weight^T + bias + x -> fp32
    gemm_h<1><<<dim3(DD / 128, RR / 128), 256, GSMEMH>>>(
        (const __half*)pxnh, (const __half*)powh, nullptr, out, ob, x, DD, DD);
}